// round 1
// baseline (speedup 1.0000x reference)
#include <cuda_runtime.h>
#include <cstddef>

// Scratch (static __device__ — no allocations allowed).
// S (softmaxed weights): (256+128+64+32) f-slices * 4096 floats = 1,966,080
__device__ float g_S[1966080];
__device__ float g_hA[2097152];   // 512*256*16 (layer1 out, reused by layer3 out)
__device__ float g_hB[1048576];   // 512*128*16 (layer2 out, reused by layer4 out)

// ---------------------------------------------------------------------------
// Kernel 1: per-column softmax of all four weight tensors.
// Column = (layer, f, k); softmax over m = 0..255 with stride 16.
// 7680 columns total. Memory-bound, ~24MB traffic -> a few microseconds.
// ---------------------------------------------------------------------------
__global__ void wsoftmax_kernel(const float* __restrict__ W1,
                                const float* __restrict__ W2,
                                const float* __restrict__ W3,
                                const float* __restrict__ W4)
{
    int col = blockIdx.x * blockDim.x + threadIdx.x;
    if (col >= 7680) return;
    const float* W; float* S; int local;
    if (col < 4096)      { W = W1; S = g_S;           local = col;        }
    else if (col < 6144) { W = W2; S = g_S + 1048576; local = col - 4096; }
    else if (col < 7168) { W = W3; S = g_S + 1572864; local = col - 6144; }
    else                 { W = W4; S = g_S + 1835008; local = col - 7168; }
    int f = local >> 4;
    int k = local & 15;
    const float* w = W + (size_t)f * 4096 + k;
    float*       s = S + (size_t)f * 4096 + k;

    float mx = -1e30f;
    #pragma unroll 4
    for (int m = 0; m < 256; m++) mx = fmaxf(mx, w[m * 16]);
    float sum = 0.f;
    #pragma unroll 4
    for (int m = 0; m < 256; m++) {
        float e = __expf(w[m * 16] - mx);
        s[m * 16] = e;
        sum += e;
    }
    float inv = 1.f / sum;
    #pragma unroll 4
    for (int m = 0; m < 256; m++) s[m * 16] *= inv;
}

// ---------------------------------------------------------------------------
// Kernel 2: one SPN layer.
//   in : hin (N=512, F_in, 16)
//   out: hout(N, F_in/2, 16)
// Block = (f_out, n-tile of 128). Each thread owns one n:
//   a_i = exp(l_i - lmax), b_j = exp(r_j - rmax)   (32 MUFU.EX2)
//   acc_k = sum_{i,j} a_i*b_j * S_f[(i*16+j)*16 + k]   (16 FMUL + 256*16 FFMA)
//   out_k = log(acc_k) + lmax + rmax
// S_f lives in smem (16KB), read as broadcast LDS.128 (cheap on crossbar).
// b lives fully in registers; a in a pad-17 smem row (per-thread private,
// conflict-free, allows rolled i-loop without local-mem spill).
// ---------------------------------------------------------------------------
__global__ void __launch_bounds__(128) layer_kernel(
    const float* __restrict__ hin, const float* __restrict__ Sall,
    float* __restrict__ hout, int F_in, int s_off)
{
    const int f   = blockIdx.x;
    const int tid = threadIdx.x;
    const int n   = blockIdx.y * 128 + tid;
    const int F_out = F_in >> 1;

    __shared__ float Ssm[4096];
    __shared__ float Asm[128 * 17];

    // Cooperative load of S_f (4096 floats) into smem, coalesced float4.
    {
        const float4* Sg  = (const float4*)(Sall + (size_t)s_off + (size_t)f * 4096);
        float4*       Ss4 = (float4*)Ssm;
        #pragma unroll
        for (int i = 0; i < 8; i++) Ss4[tid + 128 * i] = Sg[tid + 128 * i];
    }

    // Phase 1: per-thread load of left/right child vectors (32 contiguous floats)
    const float4* hp = (const float4*)(hin + ((size_t)n * F_in + 2 * f) * 16);
    float v[32];
    #pragma unroll
    for (int i = 0; i < 8; i++) ((float4*)v)[i] = hp[i];

    float lmax = v[0], rmax = v[16];
    #pragma unroll
    for (int i = 1; i < 16; i++) {
        lmax = fmaxf(lmax, v[i]);
        rmax = fmaxf(rmax, v[16 + i]);
    }
    float* arow = Asm + tid * 17;
    float breg[16];
    #pragma unroll
    for (int i = 0; i < 16; i++) {
        arow[i] = __expf(v[i] - lmax);
        breg[i] = __expf(v[16 + i] - rmax);
    }
    __syncthreads();   // for Ssm only (Asm row is per-thread private)

    // Phase 2: bilinear contraction, FFMA-bound mainloop.
    float acc[16];
    #pragma unroll
    for (int k = 0; k < 16; k++) acc[k] = 0.f;

    const float4* S4 = (const float4*)Ssm;
    #pragma unroll 2
    for (int i = 0; i < 16; i++) {
        const float ai = arow[i];
        #pragma unroll
        for (int j = 0; j < 16; j++) {
            const float p = ai * breg[j];
            const int m = (i * 16 + j) * 4;
            float4 s0 = S4[m + 0];
            float4 s1 = S4[m + 1];
            float4 s2 = S4[m + 2];
            float4 s3 = S4[m + 3];
            acc[0]  += p * s0.x; acc[1]  += p * s0.y; acc[2]  += p * s0.z; acc[3]  += p * s0.w;
            acc[4]  += p * s1.x; acc[5]  += p * s1.y; acc[6]  += p * s1.z; acc[7]  += p * s1.w;
            acc[8]  += p * s2.x; acc[9]  += p * s2.y; acc[10] += p * s2.z; acc[11] += p * s2.w;
            acc[12] += p * s3.x; acc[13] += p * s3.y; acc[14] += p * s3.z; acc[15] += p * s3.w;
        }
    }

    const float base = lmax + rmax;
    float o[16];
    #pragma unroll
    for (int k = 0; k < 16; k++) o[k] = __logf(acc[k]) + base;

    float4* op = (float4*)(hout + ((size_t)n * F_out + f) * 16);
    #pragma unroll
    for (int q = 0; q < 4; q++) op[q] = ((float4*)o)[q];
}

// ---------------------------------------------------------------------------
// Kernel 3: root. hs[n][c] = sum_f h4[n][f][c] (f=0..31), then
// out[n] = logsumexp_c( hs[n][c] + log_softmax(W_root)[c] ).
// ---------------------------------------------------------------------------
__global__ void root_kernel(const float* __restrict__ h4,
                            const float* __restrict__ Wroot,
                            float* __restrict__ out)
{
    int n = blockIdx.x * blockDim.x + threadIdx.x;
    if (n >= 512) return;

    float s[16];
    #pragma unroll
    for (int k = 0; k < 16; k++) s[k] = 0.f;

    const float4* hp = (const float4*)(h4 + (size_t)n * 512);  // 32 f * 16 c
    #pragma unroll
    for (int t = 0; t < 128; t++) {
        float4 q = hp[t];
        const int k0 = (t & 3) * 4;
        s[k0 + 0] += q.x; s[k0 + 1] += q.y; s[k0 + 2] += q.z; s[k0 + 3] += q.w;
    }

    float w[16];
    #pragma unroll
    for (int k = 0; k < 16; k++) w[k] = Wroot[k];
    float wm = w[0];
    #pragma unroll
    for (int k = 1; k < 16; k++) wm = fmaxf(wm, w[k]);
    float Z = 0.f;
    #pragma unroll
    for (int k = 0; k < 16; k++) Z += __expf(w[k] - wm);
    const float lz = __logf(Z) + wm;          // logsumexp(w)

    float t[16];
    float tm = -1e30f;
    #pragma unroll
    for (int k = 0; k < 16; k++) {
        t[k] = s[k] + w[k] - lz;
        tm = fmaxf(tm, t[k]);
    }
    float ss = 0.f;
    #pragma unroll
    for (int k = 0; k < 16; k++) ss += __expf(t[k] - tm);
    out[n] = __logf(ss) + tm;
}

// ---------------------------------------------------------------------------
// kernel_launch: 6 launches, graph-capturable, allocation-free.
// Inputs (metadata order): x, W1, W2, W3, W4, W_root. Output: 512 floats.
// ---------------------------------------------------------------------------
extern "C" void kernel_launch(void* const* d_in, const int* in_sizes, int n_in,
                              void* d_out, int out_size)
{
    const float* x  = (const float*)d_in[0];
    const float* W1 = (const float*)d_in[1];
    const float* W2 = (const float*)d_in[2];
    const float* W3 = (const float*)d_in[3];
    const float* W4 = (const float*)d_in[4];
    const float* Wr = (const float*)d_in[5];
    float* out = (float*)d_out;

    float *S, *hA, *hB;
    cudaGetSymbolAddress((void**)&S,  g_S);
    cudaGetSymbolAddress((void**)&hA, g_hA);
    cudaGetSymbolAddress((void**)&hB, g_hB);

    wsoftmax_kernel<<<30, 256>>>(W1, W2, W3, W4);

    // layer 1: F 512 -> 256
    layer_kernel<<<dim3(256, 4), 128>>>(x,  S, hA, 512, 0);
    // layer 2: F 256 -> 128
    layer_kernel<<<dim3(128, 4), 128>>>(hA, S, hB, 256, 1048576);
    // layer 3: F 128 -> 64
    layer_kernel<<<dim3(64, 4),  128>>>(hB, S, hA, 128, 1572864);
    // layer 4: F 64 -> 32
    layer_kernel<<<dim3(32, 4),  128>>>(hA, S, hB, 64,  1835008);

    root_kernel<<<4, 128>>>(hB, Wr, out);
}